// round 6
// baseline (speedup 1.0000x reference)
#include <cuda_runtime.h>
#include <math.h>

#define NLEV   16
#define NDENSE 12
#define NCONS  4
#define TSIZE  524288
#define HPRIME 2654435761u
#define HMASK  524287u
#define BLK    256

// Unified per-level params (dense levels hardcoded, hash levels from lengths).
struct LevelParams { float gs; int res; int n; int pad; };
__device__ LevelParams g_lp[NLEV];

__global__ void setup_kernel(const int* __restrict__ lengths, int L)
{
    if (threadIdx.x == 0 && blockIdx.x == 0) {
        // Dense resolutions: float32 np.power chain, margins all >> ulp error.
        const int rd[NDENSE] = {16,22,30,42,58,80,111,153,212,294,406,561};
        for (int i = 0; i < NDENSE; i++) {
            g_lp[i].res = rd[i];
            g_lp[i].gs  = (float)(2048.0 / (double)rd[i]);
            g_lp[i].n   = 0;
        }
        for (int i = 0; i < NCONS; i++) {
            int li  = (i < L) ? i : (L - 1);
            int len = lengths[li];                    // (res+1)^2
            int res = (int)(sqrt((double)len) + 0.5) - 1;
            g_lp[NDENSE + i].res = res;
            g_lp[NDENSE + i].n   = len;
            g_lp[NDENSE + i].gs  = (float)(2048.0 / (double)res);
        }
    }
}

// XLA:GPU emits approximate full-range division (div.full.f32) for f32 divide.
// Required for bit-exact bl = floor(x/gs) at cell boundaries.
__device__ __forceinline__ float div_full(float a, float b)
{
    float r;
    asm("div.full.f32 %0, %1, %2;" : "=f"(r) : "f"(a), "f"(b));
    return r;
}

// Cold path: exact replica of jnp.searchsorted(tk,2h)->where(k==n,0,k)->tv[k]
// for all 4 corners. __noinline__ keeps its register needs off the hot path.
__device__ __noinline__ void cons_fallback(const int* __restrict__ tk,
                                           const int* __restrict__ tv,
                                           int maxP, int li, int n,
                                           unsigned g0, unsigned g1,
                                           int* out4)
{
    long long ro = (long long)li * maxP;
    unsigned hs[4];
    hs[0] = (g0        ^ (g1        * HPRIME)) & HMASK;
    hs[1] = (g0        ^ ((g1 + 1u) * HPRIME)) & HMASK;
    hs[2] = ((g0 + 1u) ^ (g1        * HPRIME)) & HMASK;
    hs[3] = ((g0 + 1u) ^ ((g1 + 1u) * HPRIME)) & HMASK;
#pragma unroll
    for (int k = 0; k < 4; k++) {
        int q  = 2 * (int)hs[k];
        int lo = 0, hi = n;
        while (lo < hi) {
            int mid = (lo + hi) >> 1;
            if (__ldg(tk + ro + mid) < q) lo = mid + 1; else hi = mid;
        }
        if (lo == n) lo = 0;
        out4[k] = __ldg(tv + ro + lo);
    }
}

// 4 threads per point; lane role g = t&3 owns levels {4g..4g+3}.
// g<3 lanes: all-dense (adjacent corner pairs -> LDG.128 trick).
// g=3 lane: all 4 hash levels (independent random corners -> LDG.64 x4).
// Within one warp instruction, 8 lanes share a level -> coarse-level line merge.
__global__ __launch_bounds__(BLK, 4)
void hashgrid_kernel(const float* __restrict__ x,
                     const float* __restrict__ tables,
                     const int*   __restrict__ tk,
                     const int*   __restrict__ tv,
                     int maxP,
                     float* __restrict__ out,
                     int npts)
{
    const int t = blockIdx.x * BLK + threadIdx.x;
    const int p = t >> 2;
    const int g = t & 3;
    const bool valid = (p < npts);
    const int  pl = valid ? p : (npts - 1);

    const float2 xv = __ldg((const float2*)x + pl);
    const float x0 = xv.x, x1 = xv.y;
    const size_t idxbase = (size_t)npts * 32;
    const int lvl0 = 4 * g;

    int   idxs[16];
    float w0s[4], w1s[4];

    // ---- phase 1: indices + weights; idx stores issued immediately ----
#pragma unroll
    for (int j = 0; j < 4; j++) {
        const int lvl = lvl0 + j;
        const LevelParams lp = g_lp[lvl];
        const int   res = lp.res;
        const float gs  = lp.gs;

        float q0  = div_full(x0, gs);
        float q1  = div_full(x1, gs);
        float b0f = floorf(q0), b1f = floorf(q1);
        int   b0  = (int)b0f,   b1  = (int)b1f;
        float mn0 = b0f * gs,   mn1 = b1f * gs;
        w0s[j] = __fdiv_rn(x0 - mn0, (mn0 + gs) - mn0);
        w1s[j] = __fdiv_rn(x1 - mn1, (mn1 + gs) - mn1);

        if (lvl < NDENSE) {
            int i00 = b0 * res + b1;
            idxs[4 * j + 0] = i00;
            idxs[4 * j + 1] = i00 + 1;
            idxs[4 * j + 2] = i00 + res;
            idxs[4 * j + 3] = i00 + res + 1;
        } else {
            if ((unsigned)b0 < (unsigned)res && (unsigned)b1 < (unsigned)res) {
                // All 4 corners present in table => searchsorted returns the hash.
                unsigned g0 = (unsigned)b0, g1 = (unsigned)b1;
                idxs[4 * j + 0] = (int)((g0        ^ (g1        * HPRIME)) & HMASK);
                idxs[4 * j + 1] = (int)((g0        ^ ((g1 + 1u) * HPRIME)) & HMASK);
                idxs[4 * j + 2] = (int)(((g0 + 1u) ^ (g1        * HPRIME)) & HMASK);
                idxs[4 * j + 3] = (int)(((g0 + 1u) ^ ((g1 + 1u) * HPRIME)) & HMASK);
            } else {
                cons_fallback(tk, tv, maxP, lvl - NDENSE, lp.n,
                              (unsigned)b0, (unsigned)b1, &idxs[4 * j]);
            }
        }

        if (valid) {
            float4 v = make_float4((float)idxs[4 * j + 0], (float)idxs[4 * j + 1],
                                   (float)idxs[4 * j + 2], (float)idxs[4 * j + 3]);
            __stcs((float4*)(out + idxbase + ((size_t)lvl * npts + p) * 4), v);
        }
    }

    // ---- phase 2: gathers, issued back-to-back for MLP ----
    float2 e[16];
    if (g < 3) {
        // Dense: corner pairs (i00,i01) / (i10,i11) are adjacent 8B entries.
        // Aligned-down LDG.128 covers the pair when i00 even; odd case adds one
        // predicated LDG.64. Expected line accesses per pair ~1.06.
#pragma unroll
        for (int j = 0; j < 4; j++) {
            const int lvl = lvl0 + j;
            const float2* tb  = (const float2*)tables + (size_t)lvl * TSIZE;
            const float4* tb4 = (const float4*)tb;
#pragma unroll
            for (int pr = 0; pr < 2; pr++) {
                int ibase = idxs[4 * j + 2 * pr];
                float4 lo = __ldg(tb4 + (ibase >> 1));
                float2 hi = make_float2(0.f, 0.f);
                bool odd = (ibase & 1);
                if (odd) hi = __ldg(tb + ibase + 1);
                e[4 * j + 2 * pr]     = odd ? make_float2(lo.z, lo.w)
                                            : make_float2(lo.x, lo.y);
                e[4 * j + 2 * pr + 1] = odd ? hi : make_float2(lo.z, lo.w);
            }
        }
    } else {
        // Hash levels: 16 independent random corners.
#pragma unroll
        for (int j = 0; j < 4; j++) {
            const int lvl = lvl0 + j;
            const float2* tb = (const float2*)tables + (size_t)lvl * TSIZE;
#pragma unroll
            for (int k = 0; k < 4; k++)
                e[4 * j + k] = __ldg(tb + idxs[4 * j + k]);
        }
    }

    // ---- phase 3: interpolate + two contiguous STG.128 feat stores ----
    if (valid) {
        float f[8];
#pragma unroll
        for (int j = 0; j < 4; j++) {
            float w0 = w0s[j], w1 = w1s[j];
            float om0 = 1.0f - w0, om1 = 1.0f - w1;
            float2 e00 = e[4 * j + 0], e01 = e[4 * j + 1];
            float2 e10 = e[4 * j + 2], e11 = e[4 * j + 3];
            float c0x = e00.x * om1 + e01.x * w1;
            float c1x = e10.x * om1 + e11.x * w1;
            float c0y = e00.y * om1 + e01.y * w1;
            float c1y = e10.y * om1 + e11.y * w1;
            f[2 * j]     = c0x * om0 + c1x * w0;
            f[2 * j + 1] = c0y * om0 + c1y * w0;
        }
        float* dst = out + (size_t)p * 32 + 8 * g;     // contiguous lane slice
        __stcs((float4*)dst,       make_float4(f[0], f[1], f[2], f[3]));
        __stcs((float4*)(dst + 4), make_float4(f[4], f[5], f[6], f[7]));
    }
}

extern "C" void kernel_launch(void* const* d_in, const int* in_sizes, int n_in,
                              void* d_out, int out_size)
{
    const float* x       = (const float*)d_in[0];
    const float* tables  = (const float*)d_in[1];
    const int*   tk      = (const int*)d_in[2];
    const int*   tv      = (const int*)d_in[3];
    const int*   lengths = (const int*)d_in[4];

    int L    = in_sizes[4];
    int maxP = in_sizes[2] / (L > 0 ? L : 1);
    int npts = in_sizes[0] / 2;

    setup_kernel<<<1, 32>>>(lengths, L);

    long long nthreads = 4LL * npts;
    int blocks = (int)((nthreads + BLK - 1) / BLK);
    hashgrid_kernel<<<blocks, BLK>>>(x, tables, tk, tv, maxP, (float*)d_out, npts);
}

// round 7
// speedup vs baseline: 1.2676x; 1.2676x over previous
#include <cuda_runtime.h>
#include <math.h>

#define NLEV   16
#define NDENSE 12
#define NCONS  4
#define TSIZE  524288
#define HPRIME 2654435761u
#define HMASK  524287u
#define BLK    256

// Unified per-level params (dense levels hardcoded, hash levels from lengths).
struct LevelParams { float gs; int res; int n; int pad; };
__device__ LevelParams g_lp[NLEV];

__global__ void setup_kernel(const int* __restrict__ lengths, int L)
{
    if (threadIdx.x == 0 && blockIdx.x == 0) {
        // Dense resolutions: float32 np.power chain, margins all >> ulp error.
        const int rd[NDENSE] = {16,22,30,42,58,80,111,153,212,294,406,561};
        for (int i = 0; i < NDENSE; i++) {
            g_lp[i].res = rd[i];
            g_lp[i].gs  = (float)(2048.0 / (double)rd[i]);
            g_lp[i].n   = 0;
        }
        for (int i = 0; i < NCONS; i++) {
            int li  = (i < L) ? i : (L - 1);
            int len = lengths[li];                    // (res+1)^2
            int res = (int)(sqrt((double)len) + 0.5) - 1;
            g_lp[NDENSE + i].res = res;
            g_lp[NDENSE + i].n   = len;
            g_lp[NDENSE + i].gs  = (float)(2048.0 / (double)res);
        }
    }
}

// XLA:GPU emits approximate full-range division (div.full.f32) for f32 divide.
// Required for bit-exact bl = floor(x/gs) at cell boundaries.
__device__ __forceinline__ float div_full(float a, float b)
{
    float r;
    asm("div.full.f32 %0, %1, %2;" : "=f"(r) : "f"(a), "f"(b));
    return r;
}

// Exact replica of jnp.searchsorted(tk_row, 2h) -> where(k==n,0,k) -> tv[k].
// Fully inlined, returns by value: NO address-taken arrays (R6 lesson — taking
// &idxs[] demotes the whole array to local memory).
__device__ __forceinline__ int cons_lookup(const int* __restrict__ tk,
                                           const int* __restrict__ tv,
                                           long long rowoff, int n, unsigned h)
{
    int q  = 2 * (int)h;
    int lo = 0, hi = n;
    while (lo < hi) {
        int mid = (lo + hi) >> 1;
        if (__ldg(tk + rowoff + mid) < q) lo = mid + 1; else hi = mid;
    }
    if (lo == n) lo = 0;
    return __ldg(tv + rowoff + lo);
}

// 4 threads per point; lane role g = t&3 owns levels {4g..4g+3}.
// g<3 lanes: all-dense (adjacent corner pairs -> LDG.128 trick).
// g=3 lane: all 4 hash levels (independent random corners -> LDG.64 x4).
// Lane's feats = contiguous 8-float slice -> ONE 256-bit store (Blackwell v8).
__global__ __launch_bounds__(BLK, 4)
void hashgrid_kernel(const float* __restrict__ x,
                     const float* __restrict__ tables,
                     const int*   __restrict__ tk,
                     const int*   __restrict__ tv,
                     int maxP,
                     float* __restrict__ out,
                     int npts)
{
    const int t = blockIdx.x * BLK + threadIdx.x;
    const int p = t >> 2;
    const int g = t & 3;
    const bool valid = (p < npts);
    const int  pl = valid ? p : (npts - 1);

    const float2 xv = __ldg((const float2*)x + pl);
    const float x0 = xv.x, x1 = xv.y;
    const size_t idxbase = (size_t)npts * 32;
    const int lvl0 = 4 * g;

    int   idxs[16];
    float w0s[4], w1s[4];

    // ---- phase 1: indices + weights for this lane's 4 levels ----
#pragma unroll
    for (int j = 0; j < 4; j++) {
        const int lvl = lvl0 + j;
        const LevelParams lp = g_lp[lvl];
        const int   res = lp.res;
        const float gs  = lp.gs;

        float q0  = div_full(x0, gs);
        float q1  = div_full(x1, gs);
        float b0f = floorf(q0), b1f = floorf(q1);
        int   b0  = (int)b0f,   b1  = (int)b1f;
        float mn0 = b0f * gs,   mn1 = b1f * gs;
        w0s[j] = __fdiv_rn(x0 - mn0, (mn0 + gs) - mn0);
        w1s[j] = __fdiv_rn(x1 - mn1, (mn1 + gs) - mn1);

        if (lvl < NDENSE) {
            int i00 = b0 * res + b1;
            idxs[4 * j + 0] = i00;
            idxs[4 * j + 1] = i00 + 1;
            idxs[4 * j + 2] = i00 + res;
            idxs[4 * j + 3] = i00 + res + 1;
        } else {
            unsigned g0 = (unsigned)b0, g1 = (unsigned)b1;
            unsigned h00 = (g0        ^ (g1        * HPRIME)) & HMASK;
            unsigned h01 = (g0        ^ ((g1 + 1u) * HPRIME)) & HMASK;
            unsigned h10 = ((g0 + 1u) ^ (g1        * HPRIME)) & HMASK;
            unsigned h11 = ((g0 + 1u) ^ ((g1 + 1u) * HPRIME)) & HMASK;

            if ((unsigned)b0 < (unsigned)res && (unsigned)b1 < (unsigned)res) {
                // All 4 corners present in table => searchsorted returns the hash.
                idxs[4 * j + 0] = (int)h00; idxs[4 * j + 1] = (int)h01;
                idxs[4 * j + 2] = (int)h10; idxs[4 * j + 3] = (int)h11;
            } else {
                int li = lvl - NDENSE;
                long long ro = (long long)li * maxP;
                int n = lp.n;
                idxs[4 * j + 0] = cons_lookup(tk, tv, ro, n, h00);
                idxs[4 * j + 1] = cons_lookup(tk, tv, ro, n, h01);
                idxs[4 * j + 2] = cons_lookup(tk, tv, ro, n, h10);
                idxs[4 * j + 3] = cons_lookup(tk, tv, ro, n, h11);
            }
        }
    }

    // ---- phase 2: gathers, issued back-to-back for MLP ----
    float2 e[16];
    if (g < 3) {
        // Dense: corner pairs (i00,i01) / (i10,i11) are adjacent 8B entries.
        // Aligned-down LDG.128 covers the pair when i00 even; odd adds one
        // predicated LDG.64. Avg 1.5 line-accesses per pair vs 2.0.
#pragma unroll
        for (int j = 0; j < 4; j++) {
            const int lvl = lvl0 + j;
            const float2* tb  = (const float2*)tables + (size_t)lvl * TSIZE;
            const float4* tb4 = (const float4*)tb;
#pragma unroll
            for (int pr = 0; pr < 2; pr++) {
                int ibase = idxs[4 * j + 2 * pr];
                float4 lo = __ldg(tb4 + (ibase >> 1));
                float2 hi = make_float2(0.f, 0.f);
                bool odd = (ibase & 1);
                if (odd) hi = __ldg(tb + ibase + 1);
                e[4 * j + 2 * pr]     = odd ? make_float2(lo.z, lo.w)
                                            : make_float2(lo.x, lo.y);
                e[4 * j + 2 * pr + 1] = odd ? hi : make_float2(lo.z, lo.w);
            }
        }
    } else {
        // Hash levels: 16 independent random corners.
#pragma unroll
        for (int j = 0; j < 4; j++) {
            const int lvl = lvl0 + j;
            const float2* tb = (const float2*)tables + (size_t)lvl * TSIZE;
#pragma unroll
            for (int k = 0; k < 4; k++)
                e[4 * j + k] = __ldg(tb + idxs[4 * j + k]);
        }
    }

    // ---- phase 3: idx stores (overlap gather latency) ----
    if (valid) {
#pragma unroll
        for (int j = 0; j < 4; j++) {
            const int lvl = lvl0 + j;
            float4 v = make_float4((float)idxs[4 * j + 0], (float)idxs[4 * j + 1],
                                   (float)idxs[4 * j + 2], (float)idxs[4 * j + 3]);
            __stcs((float4*)(out + idxbase + ((size_t)lvl * npts + p) * 4), v);
        }
    }

    // ---- phase 4: interpolate + ONE 256-bit feat store ----
    if (valid) {
        float f[8];
#pragma unroll
        for (int j = 0; j < 4; j++) {
            float w0 = w0s[j], w1 = w1s[j];
            float om0 = 1.0f - w0, om1 = 1.0f - w1;
            float2 e00 = e[4 * j + 0], e01 = e[4 * j + 1];
            float2 e10 = e[4 * j + 2], e11 = e[4 * j + 3];
            float c0x = e00.x * om1 + e01.x * w1;
            float c1x = e10.x * om1 + e11.x * w1;
            float c0y = e00.y * om1 + e01.y * w1;
            float c1y = e10.y * om1 + e11.y * w1;
            f[2 * j]     = c0x * om0 + c1x * w0;
            f[2 * j + 1] = c0y * om0 + c1y * w0;
        }
        float* dst = out + (size_t)p * 32 + 8 * g;     // 32B-aligned lane slice
        asm volatile(
            "st.global.cs.v8.f32 [%0], {%1,%2,%3,%4,%5,%6,%7,%8};"
            :: "l"(dst),
               "f"(f[0]), "f"(f[1]), "f"(f[2]), "f"(f[3]),
               "f"(f[4]), "f"(f[5]), "f"(f[6]), "f"(f[7])
            : "memory");
    }
}

extern "C" void kernel_launch(void* const* d_in, const int* in_sizes, int n_in,
                              void* d_out, int out_size)
{
    const float* x       = (const float*)d_in[0];
    const float* tables  = (const float*)d_in[1];
    const int*   tk      = (const int*)d_in[2];
    const int*   tv      = (const int*)d_in[3];
    const int*   lengths = (const int*)d_in[4];

    int L    = in_sizes[4];
    int maxP = in_sizes[2] / (L > 0 ? L : 1);
    int npts = in_sizes[0] / 2;

    setup_kernel<<<1, 32>>>(lengths, L);

    long long nthreads = 4LL * npts;
    int blocks = (int)((nthreads + BLK - 1) / BLK);
    hashgrid_kernel<<<blocks, BLK>>>(x, tables, tk, tv, maxP, (float*)d_out, npts);
}

// round 8
// speedup vs baseline: 1.3203x; 1.0415x over previous
#include <cuda_runtime.h>
#include <math.h>

#define NLEV   16
#define NDENSE 12
#define NCONS  4
#define TSIZE  524288
#define HPRIME 2654435761u
#define HMASK  524287u
#define BLK    256

// Shifted dense-table copy: g_shift[SHOFF[l] + k] = (table_l[2k+1], table_l[2k+2]).
// Lets an odd-based corner pair be fetched with ONE aligned LDG.128.
// Sizes per level: (res^2+res)/2 + 1 entries (pairs), offsets are compile-time.
#define SHIFT_TOTAL 330922
__device__ float4 g_shift[SHIFT_TOTAL];
__constant__ int SHOFF[13] = {0,137,391,857,1761,3473,6714,12931,24713,47292,
                              90658,173280,330922};

// Unified per-level params (dense levels hardcoded, hash levels from lengths).
struct LevelParams { float gs; int res; int n; int pad; };
__device__ LevelParams g_lp[NLEV];

__global__ void setup_kernel(const int* __restrict__ lengths, int L)
{
    if (threadIdx.x == 0 && blockIdx.x == 0) {
        // Dense resolutions: float32 np.power chain, margins all >> ulp error.
        const int rd[NDENSE] = {16,22,30,42,58,80,111,153,212,294,406,561};
        for (int i = 0; i < NDENSE; i++) {
            g_lp[i].res = rd[i];
            g_lp[i].gs  = (float)(2048.0 / (double)rd[i]);
            g_lp[i].n   = 0;
        }
        for (int i = 0; i < NCONS; i++) {
            int li  = (i < L) ? i : (L - 1);
            int len = lengths[li];                    // (res+1)^2
            int res = (int)(sqrt((double)len) + 0.5) - 1;
            g_lp[NDENSE + i].res = res;
            g_lp[NDENSE + i].n   = len;
            g_lp[NDENSE + i].gs  = (float)(2048.0 / (double)res);
        }
    }
}

// Build the shifted dense-table copy (runs inside the captured graph; ~4us).
__global__ void fill_shift_kernel(const float* __restrict__ tables)
{
    int idx = blockIdx.x * BLK + threadIdx.x;
    if (idx >= SHIFT_TOTAL) return;
    int l = 0;
#pragma unroll
    for (int i = 1; i < NDENSE; i++) if (idx >= SHOFF[i]) l = i;
    int k = idx - SHOFF[l];
    const float2* tb2 = (const float2*)tables + (size_t)l * TSIZE;
    float2 a = __ldg(tb2 + 2 * k + 1);
    float2 b = __ldg(tb2 + 2 * k + 2);
    g_shift[idx] = make_float4(a.x, a.y, b.x, b.y);
}

// XLA:GPU emits approximate full-range division (div.full.f32) for f32 divide.
// Required for bit-exact bl = floor(x/gs) at cell boundaries.
__device__ __forceinline__ float div_full(float a, float b)
{
    float r;
    asm("div.full.f32 %0, %1, %2;" : "=f"(r) : "f"(a), "f"(b));
    return r;
}

// Exact replica of jnp.searchsorted(tk_row, 2h) -> where(k==n,0,k) -> tv[k].
// Fully inlined, returns by value (address-taken arrays demote to local mem).
__device__ __forceinline__ int cons_lookup(const int* __restrict__ tk,
                                           const int* __restrict__ tv,
                                           long long rowoff, int n, unsigned h)
{
    int q  = 2 * (int)h;
    int lo = 0, hi = n;
    while (lo < hi) {
        int mid = (lo + hi) >> 1;
        if (__ldg(tk + rowoff + mid) < q) lo = mid + 1; else hi = mid;
    }
    if (lo == n) lo = 0;
    return __ldg(tv + rowoff + lo);
}

// 4 threads per point; lane role g = t&3 owns levels {4g..4g+3}.
// g<3 lanes: all-dense — each corner pair is ONE LDG.128 (even: original table,
// odd: shifted copy; same lane extraction either way, pure pointer select).
// g=3 lane: all 4 hash levels (independent random corners -> LDG.64 x4).
// Lane's feats = contiguous 8-float slice -> ONE 256-bit store.
__global__ __launch_bounds__(BLK, 4)
void hashgrid_kernel(const float* __restrict__ x,
                     const float* __restrict__ tables,
                     const int*   __restrict__ tk,
                     const int*   __restrict__ tv,
                     int maxP,
                     float* __restrict__ out,
                     int npts)
{
    const int t = blockIdx.x * BLK + threadIdx.x;
    const int p = t >> 2;
    const int g = t & 3;
    const bool valid = (p < npts);
    const int  pl = valid ? p : (npts - 1);

    const float2 xv = __ldg((const float2*)x + pl);
    const float x0 = xv.x, x1 = xv.y;
    const size_t idxbase = (size_t)npts * 32;
    const int lvl0 = 4 * g;

    int   idxs[16];
    float w0s[4], w1s[4];

    // ---- phase 1: indices + weights for this lane's 4 levels ----
#pragma unroll
    for (int j = 0; j < 4; j++) {
        const int lvl = lvl0 + j;
        const LevelParams lp = g_lp[lvl];
        const int   res = lp.res;
        const float gs  = lp.gs;

        float q0  = div_full(x0, gs);
        float q1  = div_full(x1, gs);
        float b0f = floorf(q0), b1f = floorf(q1);
        int   b0  = (int)b0f,   b1  = (int)b1f;
        float mn0 = b0f * gs,   mn1 = b1f * gs;
        w0s[j] = __fdiv_rn(x0 - mn0, (mn0 + gs) - mn0);
        w1s[j] = __fdiv_rn(x1 - mn1, (mn1 + gs) - mn1);

        if (lvl < NDENSE) {
            int i00 = b0 * res + b1;
            idxs[4 * j + 0] = i00;
            idxs[4 * j + 1] = i00 + 1;
            idxs[4 * j + 2] = i00 + res;
            idxs[4 * j + 3] = i00 + res + 1;
        } else {
            unsigned g0 = (unsigned)b0, g1 = (unsigned)b1;
            unsigned h00 = (g0        ^ (g1        * HPRIME)) & HMASK;
            unsigned h01 = (g0        ^ ((g1 + 1u) * HPRIME)) & HMASK;
            unsigned h10 = ((g0 + 1u) ^ (g1        * HPRIME)) & HMASK;
            unsigned h11 = ((g0 + 1u) ^ ((g1 + 1u) * HPRIME)) & HMASK;

            if ((unsigned)b0 < (unsigned)res && (unsigned)b1 < (unsigned)res) {
                // All 4 corners present in table => searchsorted returns the hash.
                idxs[4 * j + 0] = (int)h00; idxs[4 * j + 1] = (int)h01;
                idxs[4 * j + 2] = (int)h10; idxs[4 * j + 3] = (int)h11;
            } else {
                int li = lvl - NDENSE;
                long long ro = (long long)li * maxP;
                int n = lp.n;
                idxs[4 * j + 0] = cons_lookup(tk, tv, ro, n, h00);
                idxs[4 * j + 1] = cons_lookup(tk, tv, ro, n, h01);
                idxs[4 * j + 2] = cons_lookup(tk, tv, ro, n, h10);
                idxs[4 * j + 3] = cons_lookup(tk, tv, ro, n, h11);
            }
        }
    }

    // ---- phase 2: gathers, issued back-to-back for MLP ----
    float2 e[16];
    if (g < 3) {
        // Dense: each corner pair (ibase, ibase+1) is one aligned LDG.128.
#pragma unroll
        for (int j = 0; j < 4; j++) {
            const int lvl = lvl0 + j;
            const float4* tb4 = (const float4*)((const float2*)tables
                                                + (size_t)lvl * TSIZE);
            const float4* sh4 = g_shift + SHOFF[lvl];
#pragma unroll
            for (int pr = 0; pr < 2; pr++) {
                int ibase = idxs[4 * j + 2 * pr];
                const float4* bp = (ibase & 1) ? sh4 : tb4;
                float4 v = __ldg(bp + (ibase >> 1));
                e[4 * j + 2 * pr]     = make_float2(v.x, v.y);
                e[4 * j + 2 * pr + 1] = make_float2(v.z, v.w);
            }
        }
    } else {
        // Hash levels: 16 independent random corners.
#pragma unroll
        for (int j = 0; j < 4; j++) {
            const int lvl = lvl0 + j;
            const float2* tb = (const float2*)tables + (size_t)lvl * TSIZE;
#pragma unroll
            for (int k = 0; k < 4; k++)
                e[4 * j + k] = __ldg(tb + idxs[4 * j + k]);
        }
    }

    // ---- phase 3: idx stores (overlap gather latency) ----
    if (valid) {
#pragma unroll
        for (int j = 0; j < 4; j++) {
            const int lvl = lvl0 + j;
            float4 v = make_float4((float)idxs[4 * j + 0], (float)idxs[4 * j + 1],
                                   (float)idxs[4 * j + 2], (float)idxs[4 * j + 3]);
            __stcs((float4*)(out + idxbase + ((size_t)lvl * npts + p) * 4), v);
        }
    }

    // ---- phase 4: interpolate + ONE 256-bit feat store ----
    if (valid) {
        float f[8];
#pragma unroll
        for (int j = 0; j < 4; j++) {
            float w0 = w0s[j], w1 = w1s[j];
            float om0 = 1.0f - w0, om1 = 1.0f - w1;
            float2 e00 = e[4 * j + 0], e01 = e[4 * j + 1];
            float2 e10 = e[4 * j + 2], e11 = e[4 * j + 3];
            float c0x = e00.x * om1 + e01.x * w1;
            float c1x = e10.x * om1 + e11.x * w1;
            float c0y = e00.y * om1 + e01.y * w1;
            float c1y = e10.y * om1 + e11.y * w1;
            f[2 * j]     = c0x * om0 + c1x * w0;
            f[2 * j + 1] = c0y * om0 + c1y * w0;
        }
        float* dst = out + (size_t)p * 32 + 8 * g;     // 32B-aligned lane slice
        asm volatile(
            "st.global.cs.v8.f32 [%0], {%1,%2,%3,%4,%5,%6,%7,%8};"
            :: "l"(dst),
               "f"(f[0]), "f"(f[1]), "f"(f[2]), "f"(f[3]),
               "f"(f[4]), "f"(f[5]), "f"(f[6]), "f"(f[7])
            : "memory");
    }
}

extern "C" void kernel_launch(void* const* d_in, const int* in_sizes, int n_in,
                              void* d_out, int out_size)
{
    const float* x       = (const float*)d_in[0];
    const float* tables  = (const float*)d_in[1];
    const int*   tk      = (const int*)d_in[2];
    const int*   tv      = (const int*)d_in[3];
    const int*   lengths = (const int*)d_in[4];

    int L    = in_sizes[4];
    int maxP = in_sizes[2] / (L > 0 ? L : 1);
    int npts = in_sizes[0] / 2;

    setup_kernel<<<1, 32>>>(lengths, L);
    fill_shift_kernel<<<(SHIFT_TOTAL + BLK - 1) / BLK, BLK>>>(tables);

    long long nthreads = 4LL * npts;
    int blocks = (int)((nthreads + BLK - 1) / BLK);
    hashgrid_kernel<<<blocks, BLK>>>(x, tables, tk, tv, maxP, (float*)d_out, npts);
}

// round 9
// speedup vs baseline: 1.3390x; 1.0142x over previous
#include <cuda_runtime.h>
#include <math.h>

#define NLEV   16
#define NDENSE 12
#define NCONS  4
#define TSIZE  524288
#define HPRIME 2654435761u
#define HMASK  524287u
#define BLK    256

// Dense-level resolutions (float32 np.power chain margins all >> ulp error).
__device__ __constant__ int   RESD[NDENSE] = {16,22,30,42,58,80,111,153,212,294,406,561};
__device__ __constant__ float GSD[NDENSE] = {
    (float)(2048.0/16.0),  (float)(2048.0/22.0),  (float)(2048.0/30.0),
    (float)(2048.0/42.0),  (float)(2048.0/58.0),  (float)(2048.0/80.0),
    (float)(2048.0/111.0), (float)(2048.0/153.0), (float)(2048.0/212.0),
    (float)(2048.0/294.0), (float)(2048.0/406.0), (float)(2048.0/561.0)
};

// Shifted dense-table copy: g_shift[SHOFF[l] + k] = (table_l[2k+1], table_l[2k+2]).
// Lets an odd-based corner pair be fetched with ONE aligned LDG.128.
#define SHIFT_TOTAL 330922
__device__ float4 g_shift[SHIFT_TOTAL];
__constant__ int SHOFF[13] = {0,137,391,857,1761,3473,6714,12931,24713,47292,
                              90658,173280,330922};

// Build the shifted dense-table copy (runs inside the captured graph; ~4us).
__global__ void fill_shift_kernel(const float* __restrict__ tables)
{
    int idx = blockIdx.x * BLK + threadIdx.x;
    if (idx >= SHIFT_TOTAL) return;
    int l = 0;
#pragma unroll
    for (int i = 1; i < NDENSE; i++) if (idx >= SHOFF[i]) l = i;
    int k = idx - SHOFF[l];
    const float2* tb2 = (const float2*)tables + (size_t)l * TSIZE;
    float2 a = __ldg(tb2 + 2 * k + 1);
    float2 b = __ldg(tb2 + 2 * k + 2);
    g_shift[idx] = make_float4(a.x, a.y, b.x, b.y);
}

// XLA:GPU emits approximate full-range division (div.full.f32) for f32 divide.
// Required for bit-exact bl = floor(x/gs) at cell boundaries.
__device__ __forceinline__ float div_full(float a, float b)
{
    float r;
    asm("div.full.f32 %0, %1, %2;" : "=f"(r) : "f"(a), "f"(b));
    return r;
}

// Exact replica of jnp.searchsorted(tk_row, 2h) -> where(k==n,0,k) -> tv[k].
// Fully inlined, returns by value (address-taken arrays demote to local mem).
__device__ __forceinline__ int cons_lookup(const int* __restrict__ tk,
                                           const int* __restrict__ tv,
                                           long long rowoff, int n, unsigned h)
{
    int q  = 2 * (int)h;
    int lo = 0, hi = n;
    while (lo < hi) {
        int mid = (lo + hi) >> 1;
        if (__ldg(tk + rowoff + mid) < q) lo = mid + 1; else hi = mid;
    }
    if (lo == n) lo = 0;
    return __ldg(tv + rowoff + lo);
}

// 4 threads per point; lane role g = t&3 owns levels {4g..4g+3}.
// g<3 lanes: all-dense — each corner pair is ONE LDG.128 (even: original table,
// odd: shifted copy; identical extraction, pure pointer select, no divergence).
// g=3 lane: all 4 hash levels; CONS params computed inline from lengths:
//   len=(res+1)^2 < 2^24 is exact in f32, sqrt of exact square is exact, and
//   round_f32(2048/res) == round_f32(round_f64(2048/res)) for all res<=2048
//   (denominator bound makes double-rounding impossible). No setup kernel.
__global__ __launch_bounds__(BLK, 4)
void hashgrid_kernel(const float* __restrict__ x,
                     const float* __restrict__ tables,
                     const int*   __restrict__ tk,
                     const int*   __restrict__ tv,
                     const int*   __restrict__ lengths,
                     int L, int maxP,
                     float* __restrict__ out,
                     int npts)
{
    const int t = blockIdx.x * BLK + threadIdx.x;
    const int p = t >> 2;
    const int g = t & 3;
    const bool valid = (p < npts);
    const int  pl = valid ? p : (npts - 1);

    const float2 xv = __ldg((const float2*)x + pl);
    const float x0 = xv.x, x1 = xv.y;
    const size_t idxbase = (size_t)npts * 32;
    const int lvl0 = 4 * g;

    int   idxs[16];
    float w0s[4], w1s[4];

    // ---- phase 1: indices + weights for this lane's 4 levels ----
    if (g < 3) {
#pragma unroll
        for (int j = 0; j < 4; j++) {
            const int lvl = lvl0 + j;
            const int   res = RESD[lvl];
            const float gs  = GSD[lvl];

            float q0  = div_full(x0, gs);
            float q1  = div_full(x1, gs);
            float b0f = floorf(q0), b1f = floorf(q1);
            int   b0  = (int)b0f,   b1  = (int)b1f;
            float mn0 = b0f * gs,   mn1 = b1f * gs;
            w0s[j] = __fdiv_rn(x0 - mn0, (mn0 + gs) - mn0);
            w1s[j] = __fdiv_rn(x1 - mn1, (mn1 + gs) - mn1);

            int i00 = b0 * res + b1;
            idxs[4 * j + 0] = i00;
            idxs[4 * j + 1] = i00 + 1;
            idxs[4 * j + 2] = i00 + res;
            idxs[4 * j + 3] = i00 + res + 1;
        }
    } else {
#pragma unroll
        for (int j = 0; j < 4; j++) {
            int li  = (j < L) ? j : (L - 1);
            int len = __ldg(lengths + li);             // (res+1)^2, exact in f32
            int res = (int)__fsqrt_rn((float)len) - 1; // exact integer sqrt
            float gs = __fdiv_rn(2048.0f, (float)res); // == f64-then-f32 (proven)

            float q0  = div_full(x0, gs);
            float q1  = div_full(x1, gs);
            float b0f = floorf(q0), b1f = floorf(q1);
            int   b0  = (int)b0f,   b1  = (int)b1f;
            float mn0 = b0f * gs,   mn1 = b1f * gs;
            w0s[j] = __fdiv_rn(x0 - mn0, (mn0 + gs) - mn0);
            w1s[j] = __fdiv_rn(x1 - mn1, (mn1 + gs) - mn1);

            unsigned g0 = (unsigned)b0, g1 = (unsigned)b1;
            unsigned h00 = (g0        ^ (g1        * HPRIME)) & HMASK;
            unsigned h01 = (g0        ^ ((g1 + 1u) * HPRIME)) & HMASK;
            unsigned h10 = ((g0 + 1u) ^ (g1        * HPRIME)) & HMASK;
            unsigned h11 = ((g0 + 1u) ^ ((g1 + 1u) * HPRIME)) & HMASK;

            if ((unsigned)b0 < (unsigned)res && (unsigned)b1 < (unsigned)res) {
                // All 4 corners present in table => searchsorted returns the hash.
                idxs[4 * j + 0] = (int)h00; idxs[4 * j + 1] = (int)h01;
                idxs[4 * j + 2] = (int)h10; idxs[4 * j + 3] = (int)h11;
            } else {
                long long ro = (long long)li * maxP;
                idxs[4 * j + 0] = cons_lookup(tk, tv, ro, len, h00);
                idxs[4 * j + 1] = cons_lookup(tk, tv, ro, len, h01);
                idxs[4 * j + 2] = cons_lookup(tk, tv, ro, len, h10);
                idxs[4 * j + 3] = cons_lookup(tk, tv, ro, len, h11);
            }
        }
    }

    // ---- phase 2: gathers, issued back-to-back for MLP ----
    float2 e[16];
    if (g < 3) {
        // Dense: each corner pair (ibase, ibase+1) is one aligned LDG.128.
#pragma unroll
        for (int j = 0; j < 4; j++) {
            const int lvl = lvl0 + j;
            const float4* tb4 = (const float4*)((const float2*)tables
                                                + (size_t)lvl * TSIZE);
            const float4* sh4 = g_shift + SHOFF[lvl];
#pragma unroll
            for (int pr = 0; pr < 2; pr++) {
                int ibase = idxs[4 * j + 2 * pr];
                const float4* bp = (ibase & 1) ? sh4 : tb4;
                float4 v = __ldg(bp + (ibase >> 1));
                e[4 * j + 2 * pr]     = make_float2(v.x, v.y);
                e[4 * j + 2 * pr + 1] = make_float2(v.z, v.w);
            }
        }
    } else {
        // Hash levels: 16 independent random corners.
#pragma unroll
        for (int j = 0; j < 4; j++) {
            const int lvl = lvl0 + j;
            const float2* tb = (const float2*)tables + (size_t)lvl * TSIZE;
#pragma unroll
            for (int k = 0; k < 4; k++)
                e[4 * j + k] = __ldg(tb + idxs[4 * j + k]);
        }
    }

    // ---- phase 3: idx stores (overlap gather latency) ----
    if (valid) {
#pragma unroll
        for (int j = 0; j < 4; j++) {
            const int lvl = lvl0 + j;
            float4 v = make_float4((float)idxs[4 * j + 0], (float)idxs[4 * j + 1],
                                   (float)idxs[4 * j + 2], (float)idxs[4 * j + 3]);
            __stcs((float4*)(out + idxbase + ((size_t)lvl * npts + p) * 4), v);
        }
    }

    // ---- phase 4: interpolate + ONE 256-bit feat store ----
    if (valid) {
        float f[8];
#pragma unroll
        for (int j = 0; j < 4; j++) {
            float w0 = w0s[j], w1 = w1s[j];
            float om0 = 1.0f - w0, om1 = 1.0f - w1;
            float2 e00 = e[4 * j + 0], e01 = e[4 * j + 1];
            float2 e10 = e[4 * j + 2], e11 = e[4 * j + 3];
            float c0x = e00.x * om1 + e01.x * w1;
            float c1x = e10.x * om1 + e11.x * w1;
            float c0y = e00.y * om1 + e01.y * w1;
            float c1y = e10.y * om1 + e11.y * w1;
            f[2 * j]     = c0x * om0 + c1x * w0;
            f[2 * j + 1] = c0y * om0 + c1y * w0;
        }
        float* dst = out + (size_t)p * 32 + 8 * g;     // 32B-aligned lane slice
        asm volatile(
            "st.global.cs.v8.f32 [%0], {%1,%2,%3,%4,%5,%6,%7,%8};"
            :: "l"(dst),
               "f"(f[0]), "f"(f[1]), "f"(f[2]), "f"(f[3]),
               "f"(f[4]), "f"(f[5]), "f"(f[6]), "f"(f[7])
            : "memory");
    }
}

extern "C" void kernel_launch(void* const* d_in, const int* in_sizes, int n_in,
                              void* d_out, int out_size)
{
    const float* x       = (const float*)d_in[0];
    const float* tables  = (const float*)d_in[1];
    const int*   tk      = (const int*)d_in[2];
    const int*   tv      = (const int*)d_in[3];
    const int*   lengths = (const int*)d_in[4];

    int L    = in_sizes[4];
    int maxP = in_sizes[2] / (L > 0 ? L : 1);
    int npts = in_sizes[0] / 2;

    fill_shift_kernel<<<(SHIFT_TOTAL + BLK - 1) / BLK, BLK>>>(tables);

    long long nthreads = 4LL * npts;
    int blocks = (int)((nthreads + BLK - 1) / BLK);
    hashgrid_kernel<<<blocks, BLK>>>(x, tables, tk, tv, lengths, L, maxP,
                                     (float*)d_out, npts);
}

// round 10
// speedup vs baseline: 1.4553x; 1.0868x over previous
#include <cuda_runtime.h>
#include <math.h>

#define NLEV   16
#define NDENSE 12
#define NCONS  4
#define TSIZE  524288
#define HPRIME 2654435761u
#define HMASK  524287u
#define BLK    256

// Dense-level resolutions (float32 np.power chain margins all >> ulp error).
__device__ __constant__ int   RESD[NDENSE] = {16,22,30,42,58,80,111,153,212,294,406,561};
__device__ __constant__ float GSD[NDENSE] = {
    (float)(2048.0/16.0),  (float)(2048.0/22.0),  (float)(2048.0/30.0),
    (float)(2048.0/42.0),  (float)(2048.0/58.0),  (float)(2048.0/80.0),
    (float)(2048.0/111.0), (float)(2048.0/153.0), (float)(2048.0/212.0),
    (float)(2048.0/294.0), (float)(2048.0/406.0), (float)(2048.0/561.0)
};

// Shifted dense-table copy: g_shift[SHOFF[l] + k] = (table_l[2k+1], table_l[2k+2]).
// Lets an odd-based corner pair be fetched with ONE aligned LDG.128.
#define SHIFT_TOTAL 330922
__device__ float4 g_shift[SHIFT_TOTAL];
__constant__ int SHOFF[13] = {0,137,391,857,1761,3473,6714,12931,24713,47292,
                              90658,173280,330922};

// Build the shifted dense-table copy (runs inside the captured graph; ~4us).
__global__ void fill_shift_kernel(const float* __restrict__ tables)
{
    int idx = blockIdx.x * BLK + threadIdx.x;
    if (idx >= SHIFT_TOTAL) return;
    int l = 0;
#pragma unroll
    for (int i = 1; i < NDENSE; i++) if (idx >= SHOFF[i]) l = i;
    int k = idx - SHOFF[l];
    const float2* tb2 = (const float2*)tables + (size_t)l * TSIZE;
    float2 a = __ldg(tb2 + 2 * k + 1);
    float2 b = __ldg(tb2 + 2 * k + 2);
    g_shift[idx] = make_float4(a.x, a.y, b.x, b.y);
}

// XLA:GPU emits approximate full-range division (div.full.f32) for f32 divide.
// Required for bit-exact bl = floor(x/gs) at cell boundaries.
__device__ __forceinline__ float div_full(float a, float b)
{
    float r;
    asm("div.full.f32 %0, %1, %2;" : "=f"(r) : "f"(a), "f"(b));
    return r;
}

// Exact replica of jnp.searchsorted(tk_row, 2h) -> where(k==n,0,k) -> tv[k].
// Fully inlined, returns by value (address-taken arrays demote to local mem).
__device__ __forceinline__ int cons_lookup(const int* __restrict__ tk,
                                           const int* __restrict__ tv,
                                           long long rowoff, int n, unsigned h)
{
    int q  = 2 * (int)h;
    int lo = 0, hi = n;
    while (lo < hi) {
        int mid = (lo + hi) >> 1;
        if (__ldg(tk + rowoff + mid) < q) lo = mid + 1; else hi = mid;
    }
    if (lo == n) lo = 0;
    return __ldg(tv + rowoff + lo);
}

// 4 threads per point; lane role g = t&3 owns levels {4g..4g+3}.
// g<3 lanes: all-dense — each corner pair is ONE LDG.128 (even: original table,
// odd: shifted copy; identical extraction, pure pointer select, no divergence).
// g=3 lane: all 4 hash levels; CONS params computed inline from lengths
// (exact: len<2^24 in f32, sqrt of perfect square exact, single==double rounding
// for 2048/res with res<=2048).
// idx outputs stored inside phase 1 (shortens idxs liveness -> 48-reg fit).
__global__ __launch_bounds__(BLK, 5)
void hashgrid_kernel(const float* __restrict__ x,
                     const float* __restrict__ tables,
                     const int*   __restrict__ tk,
                     const int*   __restrict__ tv,
                     const int*   __restrict__ lengths,
                     int L, int maxP,
                     float* __restrict__ out,
                     int npts)
{
    const int t = blockIdx.x * BLK + threadIdx.x;
    const int p = t >> 2;
    const int g = t & 3;
    const bool valid = (p < npts);
    const int  pl = valid ? p : (npts - 1);

    const float2 xv = __ldg((const float2*)x + pl);
    const float x0 = xv.x, x1 = xv.y;
    const size_t idxbase = (size_t)npts * 32;
    const int lvl0 = 4 * g;

    int   idxs[16];
    float w0s[4], w1s[4];

    // ---- phase 1: indices + weights; idx outputs stored immediately ----
    if (g < 3) {
#pragma unroll
        for (int j = 0; j < 4; j++) {
            const int lvl = lvl0 + j;
            const int   res = RESD[lvl];
            const float gs  = GSD[lvl];

            float q0  = div_full(x0, gs);
            float q1  = div_full(x1, gs);
            float b0f = floorf(q0), b1f = floorf(q1);
            int   b0  = (int)b0f,   b1  = (int)b1f;
            float mn0 = b0f * gs,   mn1 = b1f * gs;
            w0s[j] = __fdiv_rn(x0 - mn0, (mn0 + gs) - mn0);
            w1s[j] = __fdiv_rn(x1 - mn1, (mn1 + gs) - mn1);

            int i00 = b0 * res + b1;
            idxs[4 * j + 0] = i00;
            idxs[4 * j + 1] = i00 + 1;
            idxs[4 * j + 2] = i00 + res;
            idxs[4 * j + 3] = i00 + res + 1;

            if (valid) {
                float4 v = make_float4((float)i00, (float)(i00 + 1),
                                       (float)(i00 + res), (float)(i00 + res + 1));
                __stcs((float4*)(out + idxbase + ((size_t)lvl * npts + p) * 4), v);
            }
        }
    } else {
#pragma unroll
        for (int j = 0; j < 4; j++) {
            const int lvl = lvl0 + j;
            int li  = (j < L) ? j : (L - 1);
            int len = __ldg(lengths + li);             // (res+1)^2, exact in f32
            int res = (int)__fsqrt_rn((float)len) - 1; // exact integer sqrt
            float gs = __fdiv_rn(2048.0f, (float)res); // == f64-then-f32 (proven)

            float q0  = div_full(x0, gs);
            float q1  = div_full(x1, gs);
            float b0f = floorf(q0), b1f = floorf(q1);
            int   b0  = (int)b0f,   b1  = (int)b1f;
            float mn0 = b0f * gs,   mn1 = b1f * gs;
            w0s[j] = __fdiv_rn(x0 - mn0, (mn0 + gs) - mn0);
            w1s[j] = __fdiv_rn(x1 - mn1, (mn1 + gs) - mn1);

            unsigned g0 = (unsigned)b0, g1 = (unsigned)b1;
            unsigned h00 = (g0        ^ (g1        * HPRIME)) & HMASK;
            unsigned h01 = (g0        ^ ((g1 + 1u) * HPRIME)) & HMASK;
            unsigned h10 = ((g0 + 1u) ^ (g1        * HPRIME)) & HMASK;
            unsigned h11 = ((g0 + 1u) ^ ((g1 + 1u) * HPRIME)) & HMASK;

            if ((unsigned)b0 < (unsigned)res && (unsigned)b1 < (unsigned)res) {
                // All 4 corners present in table => searchsorted returns the hash.
                idxs[4 * j + 0] = (int)h00; idxs[4 * j + 1] = (int)h01;
                idxs[4 * j + 2] = (int)h10; idxs[4 * j + 3] = (int)h11;
            } else {
                long long ro = (long long)li * maxP;
                idxs[4 * j + 0] = cons_lookup(tk, tv, ro, len, h00);
                idxs[4 * j + 1] = cons_lookup(tk, tv, ro, len, h01);
                idxs[4 * j + 2] = cons_lookup(tk, tv, ro, len, h10);
                idxs[4 * j + 3] = cons_lookup(tk, tv, ro, len, h11);
            }

            if (valid) {
                float4 v = make_float4((float)idxs[4 * j + 0], (float)idxs[4 * j + 1],
                                       (float)idxs[4 * j + 2], (float)idxs[4 * j + 3]);
                __stcs((float4*)(out + idxbase + ((size_t)lvl * npts + p) * 4), v);
            }
        }
    }

    // ---- phase 2: gathers, issued back-to-back for MLP; idxs die here ----
    float2 e[16];
    if (g < 3) {
        // Dense: each corner pair (ibase, ibase+1) is one aligned LDG.128.
#pragma unroll
        for (int j = 0; j < 4; j++) {
            const int lvl = lvl0 + j;
            const float4* tb4 = (const float4*)((const float2*)tables
                                                + (size_t)lvl * TSIZE);
            const float4* sh4 = g_shift + SHOFF[lvl];
#pragma unroll
            for (int pr = 0; pr < 2; pr++) {
                int ibase = idxs[4 * j + 2 * pr];
                const float4* bp = (ibase & 1) ? sh4 : tb4;
                float4 v = __ldg(bp + (ibase >> 1));
                e[4 * j + 2 * pr]     = make_float2(v.x, v.y);
                e[4 * j + 2 * pr + 1] = make_float2(v.z, v.w);
            }
        }
    } else {
        // Hash levels: 16 independent random corners.
#pragma unroll
        for (int j = 0; j < 4; j++) {
            const int lvl = lvl0 + j;
            const float2* tb = (const float2*)tables + (size_t)lvl * TSIZE;
#pragma unroll
            for (int k = 0; k < 4; k++)
                e[4 * j + k] = __ldg(tb + idxs[4 * j + k]);
        }
    }

    // ---- phase 3: interpolate + ONE 256-bit feat store ----
    if (valid) {
        float f[8];
#pragma unroll
        for (int j = 0; j < 4; j++) {
            float w0 = w0s[j], w1 = w1s[j];
            float om0 = 1.0f - w0, om1 = 1.0f - w1;
            float2 e00 = e[4 * j + 0], e01 = e[4 * j + 1];
            float2 e10 = e[4 * j + 2], e11 = e[4 * j + 3];
            float c0x = e00.x * om1 + e01.x * w1;
            float c1x = e10.x * om1 + e11.x * w1;
            float c0y = e00.y * om1 + e01.y * w1;
            float c1y = e10.y * om1 + e11.y * w1;
            f[2 * j]     = c0x * om0 + c1x * w0;
            f[2 * j + 1] = c0y * om0 + c1y * w0;
        }
        float* dst = out + (size_t)p * 32 + 8 * g;     // 32B-aligned lane slice
        asm volatile(
            "st.global.cs.v8.f32 [%0], {%1,%2,%3,%4,%5,%6,%7,%8};"
            :: "l"(dst),
               "f"(f[0]), "f"(f[1]), "f"(f[2]), "f"(f[3]),
               "f"(f[4]), "f"(f[5]), "f"(f[6]), "f"(f[7])
            : "memory");
    }
}

extern "C" void kernel_launch(void* const* d_in, const int* in_sizes, int n_in,
                              void* d_out, int out_size)
{
    const float* x       = (const float*)d_in[0];
    const float* tables  = (const float*)d_in[1];
    const int*   tk      = (const int*)d_in[2];
    const int*   tv      = (const int*)d_in[3];
    const int*   lengths = (const int*)d_in[4];

    int L    = in_sizes[4];
    int maxP = in_sizes[2] / (L > 0 ? L : 1);
    int npts = in_sizes[0] / 2;

    fill_shift_kernel<<<(SHIFT_TOTAL + BLK - 1) / BLK, BLK>>>(tables);

    long long nthreads = 4LL * npts;
    int blocks = (int)((nthreads + BLK - 1) / BLK);
    hashgrid_kernel<<<blocks, BLK>>>(x, tables, tk, tv, lengths, L, maxP,
                                     (float*)d_out, npts);
}